// round 3
// baseline (speedup 1.0000x reference)
#include <cuda_runtime.h>
#include <math.h>

#define BB 64
#define DD 256
#define NN 16
#define RR 16

// Scratch (device globals: no allocation allowed in kernel_launch)
__device__ float g_x1c[BB * DD];
__device__ float g_res1[BB * DD];
__device__ float g_x2c[BB * DD];

__device__ __forceinline__ float warp_sum(float v) {
    v += __shfl_xor_sync(0xffffffffu, v, 16);
    v += __shfl_xor_sync(0xffffffffu, v, 8);
    v += __shfl_xor_sync(0xffffffffu, v, 4);
    v += __shfl_xor_sync(0xffffffffu, v, 2);
    v += __shfl_xor_sync(0xffffffffu, v, 1);
    return v;
}

__device__ __forceinline__ float dot8(float4 a, float4 b, float4 wa, float4 wb) {
    return a.x * wa.x + a.y * wa.y + a.z * wa.z + a.w * wa.w +
           b.x * wb.x + b.y * wb.y + b.z * wb.z + b.w * wb.w;
}

// ---------------------------------------------------------------------------
// K1: rmsnorm(x_1), rmsnorm(x_2) + in-projection.
// Output columns 0..255 -> x1c, 256..511 -> res1, 512..767 -> x2c (in_w rows 0..255 w/ x2n).
// Grid: 96 blocks x 256 threads; each warp owns ONE output column for all 64 batches.
// ---------------------------------------------------------------------------
__global__ __launch_bounds__(256) void k_inproj(
    const float* __restrict__ x1, const float* __restrict__ x2,
    const float* __restrict__ norm_w, const float* __restrict__ in_w)
{
    __shared__ __align__(16) float s_nw[DD];
    __shared__ float s_sc1[BB];
    __shared__ float s_sc2[BB];

    const int tid  = threadIdx.x;
    const int lane = tid & 31;
    const int warp = tid >> 5;

    s_nw[tid] = norm_w[tid];

    // Per-row rmsnorm scales (each warp reduces 8 rows of x1 and 8 rows of x2)
    for (int i = 0; i < 8; i++) {
        int r = warp * 8 + i;
        const float4* p1 = (const float4*)(x1 + r * DD);
        float4 a = p1[lane], c = p1[lane + 32];
        float s = a.x * a.x + a.y * a.y + a.z * a.z + a.w * a.w +
                  c.x * c.x + c.y * c.y + c.z * c.z + c.w * c.w;
        s = warp_sum(s);
        if (lane == 0) s_sc1[r] = rsqrtf(s * (1.0f / DD) + 1e-5f);

        const float4* p2 = (const float4*)(x2 + r * DD);
        float4 a2 = p2[lane], c2 = p2[lane + 32];
        float s2 = a2.x * a2.x + a2.y * a2.y + a2.z * a2.z + a2.w * a2.w +
                   c2.x * c2.x + c2.y * c2.y + c2.z * c2.z + c2.w * c2.w;
        s2 = warp_sum(s2);
        if (lane == 0) s_sc2[r] = rsqrtf(s2 * (1.0f / DD) + 1e-5f);
    }
    __syncthreads();

    const int gc = blockIdx.x * 8 + warp;   // 0..767
    const float* src = (gc < 512) ? x1 : x2;
    const float* scp = (gc < 512) ? s_sc1 : s_sc2;
    const int row    = (gc < 512) ? gc : (gc - 512);

    // Weight column folded with norm_w (rmsnorm(x)*w_row = scale * sum(x*nw*w))
    const float4* wr = (const float4*)(in_w + row * DD);
    float4 w0 = wr[lane], w1 = wr[lane + 32];
    const float4* nwp = (const float4*)s_nw;
    float4 n0 = nwp[lane], n1 = nwp[lane + 32];
    w0.x *= n0.x; w0.y *= n0.y; w0.z *= n0.z; w0.w *= n0.w;
    w1.x *= n1.x; w1.y *= n1.y; w1.z *= n1.z; w1.w *= n1.w;

    for (int b = 0; b < BB; b++) {
        const float4* xr = (const float4*)(src + b * DD);
        float4 xa = xr[lane], xb = xr[lane + 32];
        float acc = dot8(xa, xb, w0, w1);
        acc = warp_sum(acc);
        if (lane == 0) {
            float v = acc * scp[b];
            if (gc < 256)      g_x1c[b * DD + gc]         = v;
            else if (gc < 512) g_res1[b * DD + gc - 256]  = v;
            else               g_x2c[b * DD + gc - 512]   = v;
        }
    }
}

// ---------------------------------------------------------------------------
// K2: one block per batch. conv+silu (4 distinct timeslots), xproj,
// dt-proj + softplus, closed-form selective scan, gate, out-proj, rmsnorm.
// ---------------------------------------------------------------------------
__global__ __launch_bounds__(256) void k_scan_out(
    const float* __restrict__ norm_w,
    const float* __restrict__ conv_w, const float* __restrict__ conv_b,
    const float* __restrict__ xproj_w,
    const float* __restrict__ dt_w, const float* __restrict__ dt_b,
    const float* __restrict__ out_w,
    const float* __restrict__ A_log, const float* __restrict__ Dvec,
    const int* __restrict__ lp,
    float* __restrict__ out)
{
    const int b    = blockIdx.x;
    const int t    = threadIdx.x;     // channel index d
    const int lane = t & 31;
    const int warp = t >> 5;

    __shared__ __align__(16) float s_x2s[4][DD];
    __shared__ float s_B[4][NN];
    __shared__ float s_Cs[NN];
    __shared__ float s_draw[4][NN];
    __shared__ __align__(16) float s_y[DD];
    __shared__ __align__(16) float s_out[DD];
    __shared__ float s_red[8];

    // --- conv + silu: 4 distinct timeslots (suffix sums of depthwise kernel) ---
    float4 cw = ((const float4*)conv_w)[t];    // conv_w[d][0][0..3]
    float cb  = conv_b[t];
    float S[4];
    S[0] = cw.w;            // t=0: w3
    S[1] = cw.z + S[0];     // t=1: w2+w3
    S[2] = cw.y + S[1];     // t=2: w1+w2+w3
    S[3] = cw.x + S[2];     // t>=3: full sum

    float x1cv = g_x1c[b * DD + t];
    float x2cv = g_x2c[b * DD + t];
    float x1r[4];
#pragma unroll
    for (int ts = 0; ts < 4; ts++) {
        float v1 = x1cv * S[ts] + cb;
        x1r[ts] = v1 / (1.0f + __expf(-v1));        // silu, kept in registers
        float v2 = x2cv * S[ts] + cb;
        s_x2s[ts][t] = v2 / (1.0f + __expf(-v2));   // silu, needed by warp dots
    }
    __syncthreads();

    // --- xdbl = x2s @ xproj_w.T  (4 timeslots x 48 cols; warp-level dots) ---
    for (int j = warp; j < 192; j += 8) {
        int ts = j / 48, c = j % 48;
        const float4* wr = (const float4*)(xproj_w + c * DD);
        float4 w0 = wr[lane], w1 = wr[lane + 32];
        const float4* xr = (const float4*)(s_x2s[ts]);
        float4 xa = xr[lane], xb = xr[lane + 32];
        float acc = dot8(xa, xb, w0, w1);
        acc = warp_sum(acc);
        if (lane == 0) {
            if (c < 16)       s_draw[ts][c]     = acc;   // delta raw
            else if (c < 32)  s_B[ts][c - 16]   = acc;   // B
            else if (ts == 3) s_Cs[c - 32]      = acc;   // C (steady only)
        }
    }
    __syncthreads();

    // --- delta = softplus(draw @ dt_w.T + dt_b) (per-channel, 4 timeslots) ---
    float dw[16];
    {
        const float4* p = (const float4*)(dt_w + t * RR);
        ((float4*)dw)[0] = p[0]; ((float4*)dw)[1] = p[1];
        ((float4*)dw)[2] = p[2]; ((float4*)dw)[3] = p[3];
    }
    float dtb = dt_b[t];
    float dts[4];
#pragma unroll
    for (int ts = 0; ts < 4; ts++) {
        float acc = dtb;
#pragma unroll
        for (int r = 0; r < 16; r++) acc += s_draw[ts][r] * dw[r];
        dts[ts] = (acc > 20.0f) ? acc : log1pf(__expf(acc));
    }

    // --- closed-form selective scan (3 explicit steps + geometric series) ---
    int l = lp ? *lp : 256;
    float m = (float)(l - 3);
    float u[4];
#pragma unroll
    for (int ts = 0; ts < 4; ts++) u[ts] = dts[ts] * x1r[ts];

    float alr[16];
    {
        const float4* p = (const float4*)(A_log + t * NN);
        ((float4*)alr)[0] = p[0]; ((float4*)alr)[1] = p[1];
        ((float4*)alr)[2] = p[2]; ((float4*)alr)[3] = p[3];
    }

    float y = 0.0f;
#pragma unroll
    for (int n = 0; n < NN; n++) {
        float a  = -__expf(alr[n]);                    // A = -exp(A_log)
        float e1 = __expf(dts[1] * a);
        float e2 = __expf(dts[2] * a);
        float e3 = __expf(dts[3] * a);
        float h = u[0] * s_B[0][n];                    // h0 = dBu0
        h = e1 * h + u[1] * s_B[1][n];                 // h1
        h = e2 * h + u[2] * s_B[2][n];                 // h2
        float p3 = __expf(m * dts[3] * a);             // dA_s^(l-3)
        float g  = 1.0f - e3;
        float geo = (g > 1e-30f) ? (1.0f - p3) / g : m;
        h = p3 * h + u[3] * s_B[3][n] * geo;           // h_{l-1}
        y += h * s_Cs[n];
    }
    y += x1r[3] * Dvec[t];                 // + x1s * D (steady slot at t=l-1)
    float res = g_res1[b * DD + t];
    y *= res / (1.0f + __expf(-res));      // * silu(res1)
    s_y[t] = y;
    __syncthreads();

    // --- out projection: y @ out_w.T (warp-level dots) ---
    const float4* yp = (const float4*)s_y;
    float4 ya = yp[lane], yb = yp[lane + 32];
    for (int i = 0; i < 32; i++) {
        int c = warp * 32 + i;
        const float4* wr = (const float4*)(out_w + c * DD);
        float4 w0 = wr[lane], w1 = wr[lane + 32];
        float acc = dot8(ya, yb, w0, w1);
        acc = warp_sum(acc);
        if (lane == 0) s_out[c] = acc;
    }
    __syncthreads();

    // --- final rmsnorm over d, write output row ---
    float v = s_out[t];
    float ss = warp_sum(v * v);
    if (lane == 0) s_red[warp] = ss;
    __syncthreads();
    float tot = 0.0f;
#pragma unroll
    for (int w = 0; w < 8; w++) tot += s_red[w];
    float scale = rsqrtf(tot * (1.0f / DD) + 1e-5f);
    out[b * DD + t] = v * scale * norm_w[t];
}

// ---------------------------------------------------------------------------
extern "C" void kernel_launch(void* const* d_in, const int* in_sizes, int n_in,
                              void* d_out, int out_size) {
    (void)in_sizes; (void)out_size;
    const float* x1      = (const float*)d_in[0];
    const float* x2      = (const float*)d_in[1];
    const float* norm_w  = (const float*)d_in[2];
    const float* conv_w  = (const float*)d_in[3];
    const float* conv_b  = (const float*)d_in[4];
    const float* in_w    = (const float*)d_in[5];
    const float* xproj_w = (const float*)d_in[6];
    const float* dt_w    = (const float*)d_in[7];
    const float* dt_b    = (const float*)d_in[8];
    const float* out_w   = (const float*)d_in[9];
    const float* A_log   = (const float*)d_in[10];
    const float* Dv      = (const float*)d_in[11];
    const int*   lp      = (n_in > 12) ? (const int*)d_in[12] : nullptr;
    float* out = (float*)d_out;

    k_inproj<<<96, 256>>>(x1, x2, norm_w, in_w);
    k_scan_out<<<64, 256>>>(norm_w, conv_w, conv_b, xproj_w, dt_w, dt_b,
                            out_w, A_log, Dv, lp, out);
}

// round 4
// speedup vs baseline: 1.7912x; 1.7912x over previous
#include <cuda_runtime.h>
#include <math.h>

#define BB 64
#define DD 256
#define NN 16
#define RR 16

// Scratch (device globals: no allocation allowed in kernel_launch)
__device__ float g_x1c[BB * DD];
__device__ float g_res1[BB * DD];
__device__ float g_x2c[BB * DD];

__device__ __forceinline__ float warp_sum(float v) {
#pragma unroll
    for (int off = 16; off; off >>= 1)
        v += __shfl_xor_sync(0xffffffffu, v, off);
    return v;
}

// Four independent butterfly reductions, interleaved for ILP (hides SHFL lat=26)
__device__ __forceinline__ void red4(float& a0, float& a1, float& a2, float& a3) {
#pragma unroll
    for (int off = 16; off; off >>= 1) {
        a0 += __shfl_xor_sync(0xffffffffu, a0, off);
        a1 += __shfl_xor_sync(0xffffffffu, a1, off);
        a2 += __shfl_xor_sync(0xffffffffu, a2, off);
        a3 += __shfl_xor_sync(0xffffffffu, a3, off);
    }
}

__device__ __forceinline__ float dot8(float4 a, float4 b, float4 wa, float4 wb) {
    return a.x * wa.x + a.y * wa.y + a.z * wa.z + a.w * wa.w +
           b.x * wb.x + b.y * wb.y + b.z * wb.z + b.w * wb.w;
}

// ---------------------------------------------------------------------------
// K1: rmsnorm + in-projection.
// 384 blocks x 256 threads. Block bid covers 2 output columns (bid*2, bid*2+1);
// each warp handles one column x 16 batches (4 warps per column).
// Columns 0..255 -> x1c, 256..511 -> res1, 512..767 -> x2c.
// ---------------------------------------------------------------------------
__global__ __launch_bounds__(256) void k_inproj(
    const float* __restrict__ x1, const float* __restrict__ x2,
    const float* __restrict__ norm_w, const float* __restrict__ in_w)
{
    __shared__ float s_sc[BB];

    const int tid  = threadIdx.x;
    const int lane = tid & 31;
    const int warp = tid >> 5;
    const int bid  = blockIdx.x;

    const int col = bid * 2 + (warp >> 2);     // 0..767 (uniform source per block)
    const int bg  = warp & 3;                  // batch group (16 batches)
    const float* src = (col < 512) ? x1 : x2;
    const int row    = (col < 512) ? col : (col - 512);

    // rmsnorm scales for all 64 batches of this block's source:
    // 8 warps x 8 batches, ILP-unrolled x4
#pragma unroll
    for (int g = 0; g < 2; g++) {
        int r0 = warp * 8 + g * 4;
        float a[4];
#pragma unroll
        for (int i = 0; i < 4; i++) {
            const float4* p = (const float4*)(src + (r0 + i) * DD);
            float4 xa = p[lane], xb = p[lane + 32];
            a[i] = dot8(xa, xb, xa, xb);
        }
        red4(a[0], a[1], a[2], a[3]);
        if (lane < 4) {
            float s = (lane == 0) ? a[0] : (lane == 1) ? a[1] : (lane == 2) ? a[2] : a[3];
            s_sc[r0 + lane] = rsqrtf(s * (1.0f / DD) + 1e-5f);
        }
    }

    // Weight column folded with norm_w
    const float4* wr = (const float4*)(in_w + row * DD);
    float4 w0 = wr[lane], w1 = wr[lane + 32];
    const float4* nwp = (const float4*)norm_w;
    float4 n0 = nwp[lane], n1 = nwp[lane + 32];
    w0.x *= n0.x; w0.y *= n0.y; w0.z *= n0.z; w0.w *= n0.w;
    w1.x *= n1.x; w1.y *= n1.y; w1.z *= n1.z; w1.w *= n1.w;

    float* dst;
    int cl;
    if (col < 256)      { dst = g_x1c;  cl = col; }
    else if (col < 512) { dst = g_res1; cl = col - 256; }
    else                { dst = g_x2c;  cl = col - 512; }

    __syncthreads();

#pragma unroll
    for (int g = 0; g < 4; g++) {
        int b0 = bg * 16 + g * 4;
        float acc[4];
#pragma unroll
        for (int i = 0; i < 4; i++) {
            const float4* xr = (const float4*)(src + (b0 + i) * DD);
            float4 xa = xr[lane], xb = xr[lane + 32];
            acc[i] = dot8(xa, xb, w0, w1);
        }
        red4(acc[0], acc[1], acc[2], acc[3]);
        if (lane < 4) {
            int bb = b0 + lane;
            float v = (lane == 0) ? acc[0] : (lane == 1) ? acc[1] : (lane == 2) ? acc[2] : acc[3];
            dst[bb * DD + cl] = v * s_sc[bb];
        }
    }
}

// ---------------------------------------------------------------------------
// K2: one block per batch, 512 threads (16 warps).
// conv+silu (4 timeslots), xproj (12 dots/warp, x4 ILP), dt+softplus,
// closed-form scan split across thread halves (n 0..7 / 8..15),
// gate, out-proj (16 dots/warp, x4 ILP), final rmsnorm.
// ---------------------------------------------------------------------------
__global__ __launch_bounds__(512, 1) void k_scan_out(
    const float* __restrict__ norm_w,
    const float* __restrict__ conv_w, const float* __restrict__ conv_b,
    const float* __restrict__ xproj_w,
    const float* __restrict__ dt_w, const float* __restrict__ dt_b,
    const float* __restrict__ out_w,
    const float* __restrict__ A_log, const float* __restrict__ Dvec,
    const int* __restrict__ lp,
    float* __restrict__ out)
{
    const int b    = blockIdx.x;
    const int t    = threadIdx.x;
    const int ch   = t & 255;
    const int half = t >> 8;
    const int lane = t & 31;
    const int warp = t >> 5;     // 0..15

    __shared__ __align__(16) float s_x2s[4][DD];
    __shared__ float s_B[4][NN];
    __shared__ float s_Cs[NN];
    __shared__ float s_draw[4][NN];
    __shared__ __align__(16) float s_yp[2 * DD];
    __shared__ __align__(16) float s_y[DD];
    __shared__ __align__(16) float s_out[DD];
    __shared__ float s_red[8];

    // --- per-channel constant prefetch (both halves, overlaps later phases) ---
    float4 cw = ((const float4*)conv_w)[ch];
    float  cb = conv_b[ch];
    float  x1cv = g_x1c[b * DD + ch];
    float  x2cv = g_x2c[b * DD + ch];
    float  dtb  = dt_b[ch];
    float dw[16];
    {
        const float4* p = (const float4*)(dt_w + ch * RR);
        ((float4*)dw)[0] = p[0]; ((float4*)dw)[1] = p[1];
        ((float4*)dw)[2] = p[2]; ((float4*)dw)[3] = p[3];
    }
    float alr[8];
    {
        const float4* p = (const float4*)(A_log + ch * NN + half * 8);
        ((float4*)alr)[0] = p[0]; ((float4*)alr)[1] = p[1];
    }

    // --- conv + silu: 4 distinct timeslots (suffix sums of depthwise kernel) ---
    float S0 = cw.w;
    float S1 = cw.z + S0;
    float S2 = cw.y + S1;
    float S3 = cw.x + S2;
    float x1r[4];
    {
        float v;
        v = x1cv * S0 + cb; x1r[0] = v / (1.0f + __expf(-v));
        v = x1cv * S1 + cb; x1r[1] = v / (1.0f + __expf(-v));
        v = x1cv * S2 + cb; x1r[2] = v / (1.0f + __expf(-v));
        v = x1cv * S3 + cb; x1r[3] = v / (1.0f + __expf(-v));
        if (half == 0) {
            v = x2cv * S0 + cb; s_x2s[0][ch] = v / (1.0f + __expf(-v));
            v = x2cv * S1 + cb; s_x2s[1][ch] = v / (1.0f + __expf(-v));
            v = x2cv * S2 + cb; s_x2s[2][ch] = v / (1.0f + __expf(-v));
            v = x2cv * S3 + cb; s_x2s[3][ch] = v / (1.0f + __expf(-v));
        }
    }
    __syncthreads();

    // --- xdbl = x2s @ xproj_w.T : 192 dots over 16 warps = 12 each, x4 ILP ---
#pragma unroll
    for (int g = 0; g < 3; g++) {
        float acc[4];
        int jj[4];
#pragma unroll
        for (int i = 0; i < 4; i++) {
            int j = warp * 12 + g * 4 + i;
            jj[i] = j;
            int ts = j / 48, c = j % 48;
            const float4* wr = (const float4*)(xproj_w + c * DD);
            float4 w0 = wr[lane], w1 = wr[lane + 32];
            const float4* xr = (const float4*)(s_x2s[ts]);
            float4 xa = xr[lane], xb = xr[lane + 32];
            acc[i] = dot8(xa, xb, w0, w1);
        }
        red4(acc[0], acc[1], acc[2], acc[3]);
        if (lane < 4) {
            int j = jj[lane];
            int ts = j / 48, c = j % 48;
            float v = (lane == 0) ? acc[0] : (lane == 1) ? acc[1] : (lane == 2) ? acc[2] : acc[3];
            if (c < 16)       s_draw[ts][c]   = v;
            else if (c < 32)  s_B[ts][c - 16] = v;
            else if (ts == 3) s_Cs[c - 32]    = v;
        }
    }
    __syncthreads();

    // --- delta = softplus(draw @ dt_w.T + dt_b), u = delta * x1s ---
    float dts[4], u[4];
#pragma unroll
    for (int ts = 0; ts < 4; ts++) {
        float acc = dtb;
#pragma unroll
        for (int r = 0; r < 16; r++) acc += s_draw[ts][r] * dw[r];
        dts[ts] = (acc > 20.0f) ? acc : log1pf(__expf(acc));
        u[ts]   = dts[ts] * x1r[ts];
    }

    // --- closed-form scan: each half handles 8 of the 16 state dims ---
    int l = lp ? *lp : 256;
    float m = (float)(l - 3);
    float y = 0.0f;
#pragma unroll
    for (int n = 0; n < 8; n++) {
        int ng = half * 8 + n;
        float a  = -__expf(alr[n]);
        float e1 = __expf(dts[1] * a);
        float e2 = __expf(dts[2] * a);
        float e3 = __expf(dts[3] * a);
        float h = u[0] * s_B[0][ng];
        h = e1 * h + u[1] * s_B[1][ng];
        h = e2 * h + u[2] * s_B[2][ng];
        float p3 = __expf(m * dts[3] * a);
        float gg = 1.0f - e3;
        float geo = (gg > 1e-30f) ? (1.0f - p3) / gg : m;
        h = p3 * h + u[3] * s_B[3][ng] * geo;
        y += h * s_Cs[ng];
    }
    s_yp[t] = y;
    __syncthreads();

    if (half == 0) {
        float yy = s_yp[ch] + s_yp[ch + 256] + x1r[3] * Dvec[ch];
        float res = g_res1[b * DD + ch];
        yy *= res / (1.0f + __expf(-res));
        s_y[ch] = yy;
    }
    __syncthreads();

    // --- out projection: 256 dots over 16 warps = 16 each, x4 ILP ---
    const float4* yp4 = (const float4*)s_y;
    float4 ya = yp4[lane], yb = yp4[lane + 32];
#pragma unroll
    for (int g = 0; g < 4; g++) {
        float acc[4];
#pragma unroll
        for (int i = 0; i < 4; i++) {
            int c = warp * 16 + g * 4 + i;
            const float4* wr = (const float4*)(out_w + c * DD);
            float4 w0 = wr[lane], w1 = wr[lane + 32];
            acc[i] = dot8(ya, yb, w0, w1);
        }
        red4(acc[0], acc[1], acc[2], acc[3]);
        if (lane < 4) {
            int c = warp * 16 + g * 4 + lane;
            s_out[c] = (lane == 0) ? acc[0] : (lane == 1) ? acc[1] : (lane == 2) ? acc[2] : acc[3];
        }
    }
    __syncthreads();

    // --- final rmsnorm over d (lower 8 warps) ---
    if (half == 0) {
        float v = s_out[ch];
        float ss = warp_sum(v * v);
        if (lane == 0) s_red[warp] = ss;
    }
    __syncthreads();
    if (half == 0) {
        float tot = 0.0f;
#pragma unroll
        for (int w = 0; w < 8; w++) tot += s_red[w];
        float scale = rsqrtf(tot * (1.0f / DD) + 1e-5f);
        out[b * DD + ch] = s_out[ch] * scale * norm_w[ch];
    }
}

// ---------------------------------------------------------------------------
extern "C" void kernel_launch(void* const* d_in, const int* in_sizes, int n_in,
                              void* d_out, int out_size) {
    (void)in_sizes; (void)out_size;
    const float* x1      = (const float*)d_in[0];
    const float* x2      = (const float*)d_in[1];
    const float* norm_w  = (const float*)d_in[2];
    const float* conv_w  = (const float*)d_in[3];
    const float* conv_b  = (const float*)d_in[4];
    const float* in_w    = (const float*)d_in[5];
    const float* xproj_w = (const float*)d_in[6];
    const float* dt_w    = (const float*)d_in[7];
    const float* dt_b    = (const float*)d_in[8];
    const float* out_w   = (const float*)d_in[9];
    const float* A_log   = (const float*)d_in[10];
    const float* Dv      = (const float*)d_in[11];
    const int*   lp      = (n_in > 12) ? (const int*)d_in[12] : nullptr;
    float* out = (float*)d_out;

    k_inproj<<<384, 256>>>(x1, x2, norm_w, in_w);
    k_scan_out<<<64, 512>>>(norm_w, conv_w, conv_b, xproj_w, dt_w, dt_b,
                            out_w, A_log, Dv, lp, out);
}